// round 8
// baseline (speedup 1.0000x reference)
#include <cuda_runtime.h>
#include <cuda_bf16.h>

// Single fused kernel, warp-parallel prologue, phase-loads-first, and a
// packed f32x2 (FFMA2) eval epilogue: each thread handles 2 batch elements
// packed into 64-bit registers, halving FMA-pipe instruction count.
//
//   A(z) = P3(z) + sqrt(1-z^2)*Q2(z) per block (x,t);  out = Re[A_x*A_t]/16.
//
// smem: coefficients pre-DUPLICATED as float2 (lo==hi), 28 entries:
//   x-block base 0:  [0..3] e_r, [4..7] e_i, [8..10] f_r, [11..13] f_i
//   t-block base 14: same layout.

typedef unsigned long long ull;

__device__ __forceinline__ ull pk2(float lo, float hi) {
    ull r; asm("mov.b64 %0, {%1, %2};" : "=l"(r) : "f"(lo), "f"(hi)); return r;
}
__device__ __forceinline__ void upk2(ull v, float& lo, float& hi) {
    asm("mov.b64 {%0, %1}, %2;" : "=f"(lo), "=f"(hi) : "l"(v));
}
__device__ __forceinline__ ull fma2(ull a, ull b, ull c) {
    ull d; asm("fma.rn.f32x2 %0, %1, %2, %3;" : "=l"(d) : "l"(a), "l"(b), "l"(c)); return d;
}
__device__ __forceinline__ ull mul2(ull a, ull b) {
    ull d; asm("mul.rn.f32x2 %0, %1, %2;" : "=l"(d) : "l"(a), "l"(b)); return d;
}

#define SGN2 0x8000000080000000ull
#define ONE2 0x3F8000003F800000ull

// v = RZ(p_{N-1}) S ... S RZ(p_0) (1,1)^T, symbolic in (z, s):
// coeff index j = power of s. out[j] = v0[j] + v1[j]. Fully unrolled.
template <int N>
__device__ __forceinline__ void chain_coeffs_T(const float2* cs, float2* out) {
    float2 v0[N], v1[N];
    v0[0] = make_float2(cs[0].x, -cs[0].y);
    v1[0] = make_float2(cs[0].x,  cs[0].y);
#pragma unroll
    for (int k = 1; k < N; k++) {
        float2 n0[N], n1[N];
#pragma unroll
        for (int j = 0; j <= k; j++) {
            n0[j] = make_float2(0.f, 0.f);
            n1[j] = make_float2(0.f, 0.f);
        }
#pragma unroll
        for (int j = 0; j < k; j++) {
            n0[j].x += v0[j].x; n0[j].y += v0[j].y;
            n1[j].x += v1[j].x; n1[j].y += v1[j].y;
            n0[j + 1].x += -v1[j].y; n0[j + 1].y += v1[j].x;
            n1[j + 1].x += -v0[j].y; n1[j + 1].y += v0[j].x;
        }
        float c = cs[k].x, s = cs[k].y;
#pragma unroll
        for (int j = 0; j <= k; j++) {
            v0[j] = make_float2(n0[j].x * c + n0[j].y * s, n0[j].y * c - n0[j].x * s);
            v1[j] = make_float2(n1[j].x * c - n1[j].y * s, n1[j].y * c + n1[j].x * s);
        }
    }
#pragma unroll
    for (int j = 0; j < N; j++)
        out[j] = make_float2(v0[j].x + v1[j].x, v0[j].y + v1[j].y);
}

// Packed eval of one block: A = P3(z) + s*Q2(z), both lanes of the f32x2.
__device__ __forceinline__ void eval_block2(ull z, ull s, const ull* C,
                                            ull& Ar, ull& Ai) {
    ull pr = fma2(C[3], z, C[2]);  pr = fma2(pr, z, C[1]);  pr = fma2(pr, z, C[0]);
    ull pi = fma2(C[7], z, C[6]);  pi = fma2(pi, z, C[5]);  pi = fma2(pi, z, C[4]);
    ull qr = fma2(C[10], z, C[9]); qr = fma2(qr, z, C[8]);
    ull qi = fma2(C[13], z, C[12]); qi = fma2(qi, z, C[11]);
    Ar = fma2(s, qr, pr);
    Ai = fma2(s, qi, pi);
}

// Scalar fallback (tail only).
__device__ __forceinline__ float eval_one_scalar(float t, float x, const float2* cf2) {
    float cf[28];
#pragma unroll
    for (int j = 0; j < 28; j++) cf[j] = cf2[j].x;
    float sx = sqrtf(fmaxf(fmaf(-x, x, 1.0f), 0.0f));
    float st = sqrtf(fmaxf(fmaf(-t, t, 1.0f), 0.0f));
    float pxr = fmaf(fmaf(fmaf(cf[3], x, cf[2]), x, cf[1]), x, cf[0]);
    float pxi = fmaf(fmaf(fmaf(cf[7], x, cf[6]), x, cf[5]), x, cf[4]);
    float qxr = fmaf(fmaf(cf[10], x, cf[9]), x, cf[8]);
    float qxi = fmaf(fmaf(cf[13], x, cf[12]), x, cf[11]);
    float Axr = fmaf(sx, qxr, pxr), Axi = fmaf(sx, qxi, pxi);
    const float* cg = cf + 14;
    float ptr_ = fmaf(fmaf(fmaf(cg[3], t, cg[2]), t, cg[1]), t, cg[0]);
    float pti = fmaf(fmaf(fmaf(cg[7], t, cg[6]), t, cg[5]), t, cg[4]);
    float qtr = fmaf(fmaf(cg[10], t, cg[9]), t, cg[8]);
    float qti = fmaf(fmaf(cg[13], t, cg[12]), t, cg[11]);
    float Atr = fmaf(st, qtr, ptr_), Ati = fmaf(st, qti, pti);
    return fmaf(Axr, Atr, -Axi * Ati);
}

__global__ void __launch_bounds__(256)
qpinn_fused(const float* __restrict__ t, const float* __restrict__ x,
            const float* __restrict__ ph_x1, const float* __restrict__ ph_x2,
            const float* __restrict__ ph_t1, const float* __restrict__ ph_t2,
            float* __restrict__ out, int n) {
    __shared__ __align__(8) float2 s_cf2[28];   // each coeff duplicated (lo==hi)

    int w = threadIdx.x >> 5;
    int lane = threadIdx.x & 31;

    // ---- 1. CRITICAL PATH FIRST: prologue warps issue their phase LDGs ----
    float p = 0.f;
    int len = (w & 1) ? 4 : 3;
    if (w < 4 && lane < len) {
        const float* ph = (w == 0) ? ph_x1 : (w == 1) ? ph_x2
                        : (w == 2) ? ph_t1 : ph_t2;
        p = ph[lane];                      // gates the barrier: issue first
    }

    // ---- 2. bulk t/x loads: needed only after the barrier ----
    int n2 = n >> 1;
    int i = blockIdx.x * blockDim.x + threadIdx.x;
    float2 tv = make_float2(0.f, 0.f), xv = make_float2(0.f, 0.f);
    if (i < n2) {
        tv = reinterpret_cast<const float2*>(t)[i];
        xv = reinterpret_cast<const float2*>(x)[i];
    }

    // ---- 3. warp-parallel chain -> duplicated coefficients (warps 0..3) ----
    if (w < 4) {
        float c = 0.f, s = 0.f;
        if (lane < len) {
            __sincosf(0.5f * p, &s, &c);   // p/2 in [0, pi]: fast path accurate
        }
        float2 cs[4];
#pragma unroll
        for (int k = 0; k < 4; k++) {
            cs[k].x = __shfl_sync(0xffffffffu, c, k);
            cs[k].y = __shfl_sync(0xffffffffu, s, k);
        }
        float scale = (w < 2) ? 0.0625f : 1.0f;   // fold global 1/16 into x-block
        float2* base = s_cf2 + ((w < 2) ? 0 : 14);
        if ((w & 1) == 0) {
            // degree-2 chain: o2 + (o0-o2) z^2 + s*(o1 z)  -> e0, e2, f1
            float2 o[3];
            chain_coeffs_T<3>(cs, o);
            if (lane == 0) {
                float v;
                v = o[2].x * scale;            base[0]  = make_float2(v, v);
                v = o[2].y * scale;            base[4]  = make_float2(v, v);
                v = (o[0].x - o[2].x) * scale; base[2]  = make_float2(v, v);
                v = (o[0].y - o[2].y) * scale; base[6]  = make_float2(v, v);
                v = o[1].x * scale;            base[9]  = make_float2(v, v);
                v = o[1].y * scale;            base[12] = make_float2(v, v);
            }
        } else {
            // degree-3 chain: o2 z + (o0-o2) z^3 + s*(o3 + (o1-o3) z^2)
            //   -> e1, e3, f0, f2
            float2 o[4];
            chain_coeffs_T<4>(cs, o);
            if (lane == 0) {
                float v;
                v = o[2].x * scale;            base[1]  = make_float2(v, v);
                v = o[2].y * scale;            base[5]  = make_float2(v, v);
                v = (o[0].x - o[2].x) * scale; base[3]  = make_float2(v, v);
                v = (o[0].y - o[2].y) * scale; base[7]  = make_float2(v, v);
                v = o[3].x * scale;            base[8]  = make_float2(v, v);
                v = o[3].y * scale;            base[11] = make_float2(v, v);
                v = (o[1].x - o[3].x) * scale; base[10] = make_float2(v, v);
                v = (o[1].y - o[3].y) * scale; base[13] = make_float2(v, v);
            }
        }
    }
    __syncthreads();

    // ---- 4. packed f32x2 eval: 2 elements per thread ----
    ull C[28];
    const ull* sc = reinterpret_cast<const ull*>(s_cf2);
#pragma unroll
    for (int j = 0; j < 28; j++) C[j] = sc[j];   // LDS.64 broadcast

    if (i < n2) {
        ull zx = pk2(xv.x, xv.y);
        ull zt = pk2(tv.x, tv.y);
        // s^2 = 1 - z^2  (fma with sign-flipped z)
        ull sx2 = fma2(zx, zx ^ SGN2, ONE2);
        ull st2 = fma2(zt, zt ^ SGN2, ONE2);
        float a, b;
        upk2(sx2, a, b);
        ull sx = pk2(sqrtf(fmaxf(a, 0.f)), sqrtf(fmaxf(b, 0.f)));
        upk2(st2, a, b);
        ull st = pk2(sqrtf(fmaxf(a, 0.f)), sqrtf(fmaxf(b, 0.f)));

        ull Axr, Axi, Atr, Ati;
        eval_block2(zx, sx, C, Axr, Axi);
        eval_block2(zt, st, C + 14, Atr, Ati);
        // out = Axr*Atr - Axi*Ati
        ull r = fma2(Axr, Atr, mul2(Axi, Ati) ^ SGN2);
        float2 o;
        upk2(r, o.x, o.y);
        reinterpret_cast<float2*>(out)[i] = o;
    }
    // tail for odd n (empty for BATCH=262144)
    if (i == 0 && (n & 1)) out[n - 1] = eval_one_scalar(t[n - 1], x[n - 1], s_cf2);
}

extern "C" void kernel_launch(void* const* d_in, const int* in_sizes, int n_in,
                              void* d_out, int out_size) {
    const float* t     = (const float*)d_in[0];
    const float* x     = (const float*)d_in[1];
    const float* ph_x1 = (const float*)d_in[2];
    const float* ph_x2 = (const float*)d_in[3];
    const float* ph_t1 = (const float*)d_in[4];
    const float* ph_t2 = (const float*)d_in[5];
    float* out = (float*)d_out;
    int n = in_sizes[0];

    int n2 = n >> 1;
    int blocks = (n2 + 255) / 256;
    if (blocks < 1) blocks = 1;
    qpinn_fused<<<blocks, 256>>>(t, x, ph_x1, ph_x2, ph_t1, ph_t2, out, n);
}

// round 9
// speedup vs baseline: 1.0280x; 1.0280x over previous
#include <cuda_runtime.h>
#include <cuda_bf16.h>

// Single fused kernel, 1 element/thread (max concurrency: 1024 CTAs):
//   warps 0..3 each own one QSP chain (x1, x2, t1, t2). Phase LDGs are the
//   FIRST memory ops issued (they gate the __syncthreads release); the bulk
//   t/x loads are issued after and complete under the prologue's shadow.
//   lanes 0..len-1: __sincosf(p/2); shfl-gather; all lanes run the tiny
//   fully-unrolled symbolic chain; lane 0 writes its DISJOINT coefficient
//   slots (len-3 chain -> e0,e2,f1 ; len-4 chain -> e1,e3,f0,f2).
//   One __syncthreads, then every thread evaluates 1 element:
//     A(z) = P3(z) + sqrt(1-z^2)*Q2(z)  per block, out = Re[A_x * A_t]/16.
//
// smem coefficient layout (28 floats):
//   x-block base 0:  [0..3] e_r, [4..7] e_i, [8..10] f_r, [11..13] f_i
//   t-block base 14: same layout.

// v = RZ(p_{N-1}) S ... S RZ(p_0) (1,1)^T, symbolic in (z, s):
// coeff index j = power of s. out[j] = v0[j] + v1[j]. Fully unrolled.
template <int N>
__device__ __forceinline__ void chain_coeffs_T(const float2* cs, float2* out) {
    float2 v0[N], v1[N];
    v0[0] = make_float2(cs[0].x, -cs[0].y);
    v1[0] = make_float2(cs[0].x,  cs[0].y);
#pragma unroll
    for (int k = 1; k < N; k++) {
        float2 n0[N], n1[N];
#pragma unroll
        for (int j = 0; j <= k; j++) {
            n0[j] = make_float2(0.f, 0.f);
            n1[j] = make_float2(0.f, 0.f);
        }
#pragma unroll
        for (int j = 0; j < k; j++) {
            n0[j].x += v0[j].x; n0[j].y += v0[j].y;
            n1[j].x += v1[j].x; n1[j].y += v1[j].y;
            n0[j + 1].x += -v1[j].y; n0[j + 1].y += v1[j].x;
            n1[j + 1].x += -v0[j].y; n1[j + 1].y += v0[j].x;
        }
        float c = cs[k].x, s = cs[k].y;
#pragma unroll
        for (int j = 0; j <= k; j++) {
            v0[j] = make_float2(n0[j].x * c + n0[j].y * s, n0[j].y * c - n0[j].x * s);
            v1[j] = make_float2(n1[j].x * c - n1[j].y * s, n1[j].y * c + n1[j].x * s);
        }
    }
#pragma unroll
    for (int j = 0; j < N; j++)
        out[j] = make_float2(v0[j].x + v1[j].x, v0[j].y + v1[j].y);
}

// A = P(z) + s*Q(z): P cubic, Q quadratic, Horner.
__device__ __forceinline__ void eval_block(float z, float s, const float* cf,
                                           float& Ar, float& Ai) {
    float pr = fmaf(cf[3], z, cf[2]);
    pr = fmaf(pr, z, cf[1]);
    pr = fmaf(pr, z, cf[0]);
    float pi = fmaf(cf[7], z, cf[6]);
    pi = fmaf(pi, z, cf[5]);
    pi = fmaf(pi, z, cf[4]);
    float qr = fmaf(cf[10], z, cf[9]);
    qr = fmaf(qr, z, cf[8]);
    float qi = fmaf(cf[13], z, cf[12]);
    qi = fmaf(qi, z, cf[11]);
    Ar = fmaf(s, qr, pr);
    Ai = fmaf(s, qi, pi);
}

__device__ __forceinline__ float eval_one(float t, float x, const float* cf) {
    float sx = sqrtf(fmaxf(fmaf(-x, x, 1.0f), 0.0f));
    float st = sqrtf(fmaxf(fmaf(-t, t, 1.0f), 0.0f));
    float Axr, Axi, Atr, Ati;
    eval_block(x, sx, cf, Axr, Axi);
    eval_block(t, st, cf + 14, Atr, Ati);
    return fmaf(Axr, Atr, -Axi * Ati);
}

__global__ void __launch_bounds__(256)
qpinn_fused(const float* __restrict__ t, const float* __restrict__ x,
            const float* __restrict__ ph_x1, const float* __restrict__ ph_x2,
            const float* __restrict__ ph_t1, const float* __restrict__ ph_t2,
            float* __restrict__ out, int n) {
    __shared__ float s_cf[28];

    int w = threadIdx.x >> 5;
    int lane = threadIdx.x & 31;

    // ---- 1. CRITICAL PATH FIRST: prologue warps issue their phase LDGs ----
    float p = 0.f;
    int len = (w & 1) ? 4 : 3;
    if (w < 4 && lane < len) {
        const float* ph = (w == 0) ? ph_x1 : (w == 1) ? ph_x2
                        : (w == 2) ? ph_t1 : ph_t2;
        p = ph[lane];                       // gates the barrier: issue first
    }

    // ---- 2. bulk t/x loads (1 elem/thread, coalesced 128B/warp) ----
    int i = blockIdx.x * blockDim.x + threadIdx.x;
    float tv = 0.f, xv = 0.f;
    if (i < n) {
        tv = t[i];
        xv = x[i];
    }

    // ---- 3. warp-parallel chain -> coefficients (warps 0..3) ----
    if (w < 4) {
        float c = 0.f, s = 0.f;
        if (lane < len) {
            __sincosf(0.5f * p, &s, &c);    // p/2 in [0, pi]: fast path accurate
        }
        float2 cs[4];
#pragma unroll
        for (int k = 0; k < 4; k++) {
            cs[k].x = __shfl_sync(0xffffffffu, c, k);
            cs[k].y = __shfl_sync(0xffffffffu, s, k);
        }
        float scale = (w < 2) ? 0.0625f : 1.0f;   // fold global 1/16 into x-block
        float* base = s_cf + ((w < 2) ? 0 : 14);
        if ((w & 1) == 0) {
            // degree-2 chain: o0 z^2 + o1 z s + o2 s^2
            //   = o2 + (o0-o2) z^2 + s*(o1 z)  -> e0, e2, f1
            float2 o[3];
            chain_coeffs_T<3>(cs, o);
            if (lane == 0) {
                base[0]  = o[2].x * scale;            base[4]  = o[2].y * scale;
                base[2]  = (o[0].x - o[2].x) * scale; base[6]  = (o[0].y - o[2].y) * scale;
                base[9]  = o[1].x * scale;            base[12] = o[1].y * scale;
            }
        } else {
            // degree-3 chain: o0 z^3 + o1 z^2 s + o2 z s^2 + o3 s^3
            //   = o2 z + (o0-o2) z^3 + s*(o3 + (o1-o3) z^2)  -> e1, e3, f0, f2
            float2 o[4];
            chain_coeffs_T<4>(cs, o);
            if (lane == 0) {
                base[1]  = o[2].x * scale;            base[5]  = o[2].y * scale;
                base[3]  = (o[0].x - o[2].x) * scale; base[7]  = (o[0].y - o[2].y) * scale;
                base[8]  = o[3].x * scale;            base[11] = o[3].y * scale;
                base[10] = (o[1].x - o[3].x) * scale; base[13] = (o[1].y - o[3].y) * scale;
            }
        }
    }
    __syncthreads();

    // ---- 4. evaluate (coefficients broadcast from smem -> regs) ----
    float cf[28];
#pragma unroll
    for (int j = 0; j < 28; j++) cf[j] = s_cf[j];

    if (i < n) {
        out[i] = eval_one(tv, xv, cf);
    }
}

extern "C" void kernel_launch(void* const* d_in, const int* in_sizes, int n_in,
                              void* d_out, int out_size) {
    const float* t     = (const float*)d_in[0];
    const float* x     = (const float*)d_in[1];
    const float* ph_x1 = (const float*)d_in[2];
    const float* ph_x2 = (const float*)d_in[3];
    const float* ph_t1 = (const float*)d_in[4];
    const float* ph_t2 = (const float*)d_in[5];
    float* out = (float*)d_out;
    int n = in_sizes[0];

    int blocks = (n + 255) / 256;
    if (blocks < 1) blocks = 1;
    qpinn_fused<<<blocks, 256>>>(t, x, ph_x1, ph_x2, ph_t1, ph_t2, out, n);
}

// round 10
// speedup vs baseline: 1.1168x; 1.0863x over previous
#include <cuda_runtime.h>
#include <cuda_bf16.h>

// Single fused kernel (best-measured config: grid 512, float2 I/O):
//   warps 0..3 each own one QSP chain (x1, x2, t1, t2). Phase LDGs are the
//   FIRST memory ops issued (they gate the __syncthreads release); the bulk
//   t/x loads are issued after and complete under the prologue's shadow.
//   lanes 0..len-1: __sincosf(p/2); shfl-gather; all lanes run the tiny
//   fully-unrolled symbolic chain; lane 0 writes its DISJOINT coefficient
//   slots (len-3 chain -> e0,e2,f1 ; len-4 chain -> e1,e3,f0,f2).
//   One __syncthreads, then every thread evaluates 2 elements:
//     A(z) = P3(z) + sqrt(1-z^2)*Q2(z)  per block, out = Re[A_x * A_t]/16.
//   Coefficients are re-broadcast post-barrier as 7x LDS.128 (16B-aligned).
//
// smem coefficient layout (28 floats, 16B aligned):
//   x-block base 0:  [0..3] e_r, [4..7] e_i, [8..10] f_r, [11..13] f_i
//   t-block base 14: same layout.

// v = RZ(p_{N-1}) S ... S RZ(p_0) (1,1)^T, symbolic in (z, s):
// coeff index j = power of s. out[j] = v0[j] + v1[j]. Fully unrolled.
template <int N>
__device__ __forceinline__ void chain_coeffs_T(const float2* cs, float2* out) {
    float2 v0[N], v1[N];
    v0[0] = make_float2(cs[0].x, -cs[0].y);
    v1[0] = make_float2(cs[0].x,  cs[0].y);
#pragma unroll
    for (int k = 1; k < N; k++) {
        float2 n0[N], n1[N];
#pragma unroll
        for (int j = 0; j <= k; j++) {
            n0[j] = make_float2(0.f, 0.f);
            n1[j] = make_float2(0.f, 0.f);
        }
#pragma unroll
        for (int j = 0; j < k; j++) {
            n0[j].x += v0[j].x; n0[j].y += v0[j].y;
            n1[j].x += v1[j].x; n1[j].y += v1[j].y;
            n0[j + 1].x += -v1[j].y; n0[j + 1].y += v1[j].x;
            n1[j + 1].x += -v0[j].y; n1[j + 1].y += v0[j].x;
        }
        float c = cs[k].x, s = cs[k].y;
#pragma unroll
        for (int j = 0; j <= k; j++) {
            v0[j] = make_float2(n0[j].x * c + n0[j].y * s, n0[j].y * c - n0[j].x * s);
            v1[j] = make_float2(n1[j].x * c - n1[j].y * s, n1[j].y * c + n1[j].x * s);
        }
    }
#pragma unroll
    for (int j = 0; j < N; j++)
        out[j] = make_float2(v0[j].x + v1[j].x, v0[j].y + v1[j].y);
}

// A = P(z) + s*Q(z): P cubic, Q quadratic, Horner.
__device__ __forceinline__ void eval_block(float z, float s, const float* cf,
                                           float& Ar, float& Ai) {
    float pr = fmaf(cf[3], z, cf[2]);
    pr = fmaf(pr, z, cf[1]);
    pr = fmaf(pr, z, cf[0]);
    float pi = fmaf(cf[7], z, cf[6]);
    pi = fmaf(pi, z, cf[5]);
    pi = fmaf(pi, z, cf[4]);
    float qr = fmaf(cf[10], z, cf[9]);
    qr = fmaf(qr, z, cf[8]);
    float qi = fmaf(cf[13], z, cf[12]);
    qi = fmaf(qi, z, cf[11]);
    Ar = fmaf(s, qr, pr);
    Ai = fmaf(s, qi, pi);
}

__device__ __forceinline__ float eval_one(float t, float x, const float* cf) {
    float sx = sqrtf(fmaxf(fmaf(-x, x, 1.0f), 0.0f));
    float st = sqrtf(fmaxf(fmaf(-t, t, 1.0f), 0.0f));
    float Axr, Axi, Atr, Ati;
    eval_block(x, sx, cf, Axr, Axi);
    eval_block(t, st, cf + 14, Atr, Ati);
    return fmaf(Axr, Atr, -Axi * Ati);
}

__global__ void __launch_bounds__(256)
qpinn_fused(const float* __restrict__ t, const float* __restrict__ x,
            const float* __restrict__ ph_x1, const float* __restrict__ ph_x2,
            const float* __restrict__ ph_t1, const float* __restrict__ ph_t2,
            float* __restrict__ out, int n) {
    __shared__ __align__(16) float s_cf[28];

    int w = threadIdx.x >> 5;
    int lane = threadIdx.x & 31;

    // ---- 1. CRITICAL PATH FIRST: prologue warps issue their phase LDGs ----
    float p = 0.f;
    int len = (w & 1) ? 4 : 3;
    if (w < 4 && lane < len) {
        const float* ph = (w == 0) ? ph_x1 : (w == 1) ? ph_x2
                        : (w == 2) ? ph_t1 : ph_t2;
        p = ph[lane];                       // gates the barrier: issue first
    }

    // ---- 2. bulk t/x loads: needed only after the barrier ----
    int n2 = n >> 1;
    int i = blockIdx.x * blockDim.x + threadIdx.x;
    float2 tv = make_float2(0.f, 0.f), xv = make_float2(0.f, 0.f);
    if (i < n2) {
        tv = reinterpret_cast<const float2*>(t)[i];
        xv = reinterpret_cast<const float2*>(x)[i];
    }

    // ---- 3. warp-parallel chain -> coefficients (warps 0..3) ----
    if (w < 4) {
        float c = 0.f, s = 0.f;
        if (lane < len) {
            __sincosf(0.5f * p, &s, &c);    // p/2 in [0, pi]: fast path accurate
        }
        float2 cs[4];
#pragma unroll
        for (int k = 0; k < 4; k++) {
            cs[k].x = __shfl_sync(0xffffffffu, c, k);
            cs[k].y = __shfl_sync(0xffffffffu, s, k);
        }
        float scale = (w < 2) ? 0.0625f : 1.0f;   // fold global 1/16 into x-block
        float* base = s_cf + ((w < 2) ? 0 : 14);
        if ((w & 1) == 0) {
            // degree-2 chain: o0 z^2 + o1 z s + o2 s^2
            //   = o2 + (o0-o2) z^2 + s*(o1 z)  -> e0, e2, f1
            float2 o[3];
            chain_coeffs_T<3>(cs, o);
            if (lane == 0) {
                base[0]  = o[2].x * scale;            base[4]  = o[2].y * scale;
                base[2]  = (o[0].x - o[2].x) * scale; base[6]  = (o[0].y - o[2].y) * scale;
                base[9]  = o[1].x * scale;            base[12] = o[1].y * scale;
            }
        } else {
            // degree-3 chain: o0 z^3 + o1 z^2 s + o2 z s^2 + o3 s^3
            //   = o2 z + (o0-o2) z^3 + s*(o3 + (o1-o3) z^2)  -> e1, e3, f0, f2
            float2 o[4];
            chain_coeffs_T<4>(cs, o);
            if (lane == 0) {
                base[1]  = o[2].x * scale;            base[5]  = o[2].y * scale;
                base[3]  = (o[0].x - o[2].x) * scale; base[7]  = (o[0].y - o[2].y) * scale;
                base[8]  = o[3].x * scale;            base[11] = o[3].y * scale;
                base[10] = (o[1].x - o[3].x) * scale; base[13] = (o[1].y - o[3].y) * scale;
            }
        }
    }
    __syncthreads();

    // ---- 4. evaluate: coefficients via 7x LDS.128 broadcast -> regs ----
    float cf[28];
    const float4* s4 = reinterpret_cast<const float4*>(s_cf);
#pragma unroll
    for (int j = 0; j < 7; j++) {
        float4 v = s4[j];
        cf[4 * j] = v.x; cf[4 * j + 1] = v.y; cf[4 * j + 2] = v.z; cf[4 * j + 3] = v.w;
    }

    if (i < n2) {
        float2 o;
        o.x = eval_one(tv.x, xv.x, cf);
        o.y = eval_one(tv.y, xv.y, cf);
        reinterpret_cast<float2*>(out)[i] = o;
    }
    // tail for odd n (empty for BATCH=262144)
    if (i == 0 && (n & 1)) out[n - 1] = eval_one(t[n - 1], x[n - 1], cf);
}

extern "C" void kernel_launch(void* const* d_in, const int* in_sizes, int n_in,
                              void* d_out, int out_size) {
    const float* t     = (const float*)d_in[0];
    const float* x     = (const float*)d_in[1];
    const float* ph_x1 = (const float*)d_in[2];
    const float* ph_x2 = (const float*)d_in[3];
    const float* ph_t1 = (const float*)d_in[4];
    const float* ph_t2 = (const float*)d_in[5];
    float* out = (float*)d_out;
    int n = in_sizes[0];

    int n2 = n >> 1;
    int blocks = (n2 + 255) / 256;
    if (blocks < 1) blocks = 1;
    qpinn_fused<<<blocks, 256>>>(t, x, ph_x1, ph_x2, ph_t1, ph_t2, out, n);
}